// round 7
// baseline (speedup 1.0000x reference)
#include <cuda_runtime.h>

// LIF neuron with cache term:
//   mem   = mem/TAU + (1 + ALPHA*cache) * x_t
//   spike = (mem - V_TH > 0); mem = (1-spike)*mem; cache = BETA*cache + (1-spike)
//
// X: [B=32, T=64, N=32768] f32 -> spikes, same shape. Pure streaming,
// compulsory traffic 512 MiB.
//
// R6 finding: DRAM idles ~24% despite three request-depth fixes ->
// the idle is CTA imbalance + tail drain (1024 CTAs / 148 SMs = 6.92,
// 16.7% work skew between 7-CTA and 6-CTA SMs). Fix: grid = 148*14
// CTAs of 128 threads — every SM gets exactly 14 CTAs (56 warps),
// zero skew, finer drain granularity. Excess threads guarded out.
// Keep the per-thread cp.async.cg 4-stage SMEM ring (barrier-free:
// each thread reads only its own 16B; wait_group orders per-thread).
//
// Division by TAU=5 via residual-corrected FMA triple — provably
// bit-identical to __fdiv_rn(x,5) for all floats. All other ops use
// explicit __f*_rn (no FMA contraction) to bit-match the XLA
// reference; a single threshold flip would cascade across T.

constexpr int B = 32;
constexpr int T = 64;
constexpr int N = 32768;
constexpr int N4 = N / 4;            // 8192 float4 per (b, t) row
constexpr int LANES = B * N4;        // 262,144
constexpr int THREADS = 128;
constexpr int SMS = 148;
constexpr int CTAS = SMS * 14;       // 2072: exactly 14 CTAs per SM
constexpr int STAGES = 4;            // smem ring depth (8KB/CTA)

__device__ __forceinline__ float div5_exact(float x) {
    const float y = 0.2f;                       // RN(1/5)
    float q = __fmul_rn(x, y);
    float r = __fmaf_rn(q, -5.0f, x);           // exact residual
    return __fmaf_rn(r, y, q);                  // == __fdiv_rn(x, 5.0f)
}

__device__ __forceinline__ float lif_step(float x, float& mem, float& cache) {
    float d = div5_exact(mem);                              // mem / TAU
    float g = __fadd_rn(1.0f, __fmul_rn(0.1f, cache));      // 1 + ALPHA*cache
    mem = __fadd_rn(d, __fmul_rn(g, x));
    bool fired = (mem > 0.5f);                              // mem - V_TH > 0
    float spike = fired ? 1.0f : 0.0f;
    mem = fired ? 0.0f : mem;                               // hard reset to 0
    cache = __fadd_rn(__fmul_rn(0.5f, cache), fired ? 0.0f : 1.0f);
    return spike;
}

__device__ __forceinline__ void cp_async16(float4* smem, const float4* gmem) {
    unsigned int s = (unsigned int)__cvta_generic_to_shared(smem);
    asm volatile("cp.async.cg.shared.global [%0], [%1], 16;"
                 :: "r"(s), "l"(gmem) : "memory");
}
__device__ __forceinline__ void cp_commit() {
    asm volatile("cp.async.commit_group;" ::: "memory");
}
template <int Nwait>
__device__ __forceinline__ void cp_wait() {
    asm volatile("cp.async.wait_group %0;" :: "n"(Nwait) : "memory");
}

__global__ __launch_bounds__(THREADS) void lif_kernel(
    const float4* __restrict__ X, float4* __restrict__ out)
{
    __shared__ float4 buf[STAGES][THREADS];

    int tid  = threadIdx.x;
    int lane = blockIdx.x * THREADS + tid;
    bool active = (lane < LANES);
    int l = active ? lane : (LANES - 1);        // clamp: inactive threads
    int b = l >> 13;                            // duplicate last lane's
    int c = l & (N4 - 1);                       // loads, skip its stores
    int base = b * (T * N4) + c;

    // Prologue: fill the ring, one commit group per stage.
#pragma unroll
    for (int s = 0; s < STAGES; ++s) {
        cp_async16(&buf[s][tid], &X[base + s * N4]);
        cp_commit();
    }

    float4 mem   = make_float4(0.f, 0.f, 0.f, 0.f);
    float4 cache = make_float4(0.f, 0.f, 0.f, 0.f);

#pragma unroll 4
    for (int t = 0; t < T; ++t) {
        cp_wait<STAGES - 1>();                // stage-t copy complete
        int slot = t & (STAGES - 1);
        float4 x = buf[slot][tid];            // LDS: only own bytes

        if (t + STAGES < T)
            cp_async16(&buf[slot][tid], &X[base + (t + STAGES) * N4]);
        cp_commit();                          // empty group at tail: legal

        float4 s;
        s.x = lif_step(x.x, mem.x, cache.x);
        s.y = lif_step(x.y, mem.y, cache.y);
        s.z = lif_step(x.z, mem.z, cache.z);
        s.w = lif_step(x.w, mem.w, cache.w);

        if (active)
            __stcs(&out[base + t * N4], s);
    }
}

extern "C" void kernel_launch(void* const* d_in, const int* in_sizes, int n_in,
                              void* d_out, int out_size) {
    const float4* X = (const float4*)d_in[0];
    float4* out = (float4*)d_out;
    lif_kernel<<<CTAS, THREADS>>>(X, out);
}

// round 8
// speedup vs baseline: 1.0031x; 1.0031x over previous
#include <cuda_runtime.h>

// LIF neuron with cache term:
//   mem   = mem/TAU + (1 + ALPHA*cache) * x_t
//   spike = (mem - V_TH > 0); mem = (1-spike)*mem; cache = BETA*cache + (1-spike)
//
// X: [B=32, T=64, N=32768] f32 -> spikes, same shape. Pure streaming,
// 512 MiB compulsory traffic, 1:1 read:write.
//
// R4-R7 falsified all schedule-side theories (request depth, L2
// prefetch, cp.async ring, CTA balance) — DRAM pinned at 73-76% in
// every variant. Remaining suspect: DRAM read<->write bus-turnaround
// on the fine-grained 1:1 interleaved mix. This round attacks the
// request stream itself:
//   * 256-bit ld/st (sm_100+ v8.f32): 1KB contiguous per warp
//     instruction, halving request fragmentation;
//   * unroll-4 with hoisted loads so ptxas front-batches 4 loads then
//     4 stores per group — longer same-direction runs per channel.
//
// Division by TAU=5 via residual-corrected FMA triple — provably
// bit-identical to __fdiv_rn(x,5) for all floats. All other ops use
// explicit __f*_rn (no FMA contraction) to bit-match the XLA
// reference; a single threshold flip would cascade across T.

constexpr int B = 32;
constexpr int T = 64;
constexpr int N = 32768;
constexpr int N8 = N / 8;            // 4096 v8-groups per (b, t) row
constexpr int THREADS = 256;
constexpr int CTAS = (B * N8) / THREADS;   // 512

__device__ __forceinline__ float div5_exact(float x) {
    const float y = 0.2f;                       // RN(1/5)
    float q = __fmul_rn(x, y);
    float r = __fmaf_rn(q, -5.0f, x);           // exact residual
    return __fmaf_rn(r, y, q);                  // == __fdiv_rn(x, 5.0f)
}

__device__ __forceinline__ float lif_step(float x, float& mem, float& cache) {
    float d = div5_exact(mem);                              // mem / TAU
    float g = __fadd_rn(1.0f, __fmul_rn(0.1f, cache));      // 1 + ALPHA*cache
    mem = __fadd_rn(d, __fmul_rn(g, x));
    bool fired = (mem > 0.5f);                              // mem - V_TH > 0
    float spike = fired ? 1.0f : 0.0f;
    mem = fired ? 0.0f : mem;                               // hard reset to 0
    cache = __fadd_rn(__fmul_rn(0.5f, cache), fired ? 0.0f : 1.0f);
    return spike;
}

__device__ __forceinline__ void ldg_v8(const float* p, float* v) {
    asm volatile(
        "ld.global.nc.v8.f32 {%0,%1,%2,%3,%4,%5,%6,%7}, [%8];"
        : "=f"(v[0]), "=f"(v[1]), "=f"(v[2]), "=f"(v[3]),
          "=f"(v[4]), "=f"(v[5]), "=f"(v[6]), "=f"(v[7])
        : "l"(p));
}

__device__ __forceinline__ void stg_v8(float* p, const float* v) {
    asm volatile(
        "st.global.v8.f32 [%0], {%1,%2,%3,%4,%5,%6,%7,%8};"
        :: "l"(p),
           "f"(v[0]), "f"(v[1]), "f"(v[2]), "f"(v[3]),
           "f"(v[4]), "f"(v[5]), "f"(v[6]), "f"(v[7])
        : "memory");
}

__global__ __launch_bounds__(THREADS) void lif_kernel(
    const float* __restrict__ X, float* __restrict__ out)
{
    int lane = blockIdx.x * THREADS + threadIdx.x;   // [0, B*N8)
    int b = lane >> 12;                               // lane / N8
    int c = (lane & (N8 - 1)) << 3;                   // float offset in row
    int base = b * (T * N) + c;                       // < 2^26, int OK

    float mem[8], cache[8];
#pragma unroll
    for (int i = 0; i < 8; ++i) { mem[i] = 0.0f; cache[i] = 0.0f; }

#pragma unroll 4
    for (int t = 0; t < T; ++t) {
        int idx = base + t * N;
        float x[8];
        ldg_v8(X + idx, x);                // 1KB/warp, front-batched

        float s[8];
#pragma unroll
        for (int i = 0; i < 8; ++i)
            s[i] = lif_step(x[i], mem[i], cache[i]);

        stg_v8(out + idx, s);              // 1KB/warp
    }
}

extern "C" void kernel_launch(void* const* d_in, const int* in_sizes, int n_in,
                              void* d_out, int out_size) {
    const float* X = (const float*)d_in[0];
    float* out = (float*)d_out;
    lif_kernel<<<CTAS, THREADS>>>(X, out);
}

// round 9
// speedup vs baseline: 1.0236x; 1.0205x over previous
#include <cuda_runtime.h>

// LIF neuron with cache term:
//   mem   = mem/TAU + (1 + ALPHA*cache) * x_t
//   spike = (mem - V_TH > 0); mem = (1-spike)*mem; cache = BETA*cache + (1-spike)
//
// X: [B=32, T=64, N=32768] f32 -> spikes, same shape. Pure streaming,
// 512 MiB compulsory, 1:1 R/W.
//
// R4-R8: five mechanistically distinct variants (register depth, L2
// prefetch, cp.async ring, perfect CTA balance, 256-bit v8 ops) all
// pin DRAM at 73-76% (~6 TB/s) — schedule-side knobs are not binding;
// that is the effective HBM ceiling for a fine-grained 1:1 R/W mix.
// This round: best-measured skeleton (R3: float4 + ldcs/stcs +
// prefetch-by-1) with TWO widely spaced lanes per thread (different
// 2MB pages -> different L2-slice/channel hash buckets) to smooth
// per-channel load — the one DRAM-side knob not yet isolated.
//
// Division by TAU=5 via residual-corrected FMA triple — provably
// bit-identical to __fdiv_rn(x,5) for all floats. All other ops use
// explicit __f*_rn (no FMA contraction) to bit-match the XLA
// reference; a single threshold flip would cascade across T.

constexpr int B = 32;
constexpr int T = 64;
constexpr int N = 32768;
constexpr int N4 = N / 4;             // 8192 float4 per (b, t) row
constexpr int LANES = B * N4;         // 262,144 float4 lanes
constexpr int HALF = LANES / 2;       // second stream offset (131,072)
constexpr int THREADS = 256;
constexpr int CTAS = HALF / THREADS;  // 512

__device__ __forceinline__ float div5_exact(float x) {
    const float y = 0.2f;                       // RN(1/5)
    float q = __fmul_rn(x, y);
    float r = __fmaf_rn(q, -5.0f, x);           // exact residual
    return __fmaf_rn(r, y, q);                  // == __fdiv_rn(x, 5.0f)
}

__device__ __forceinline__ float lif_step(float x, float& mem, float& cache) {
    float d = div5_exact(mem);                              // mem / TAU
    float g = __fadd_rn(1.0f, __fmul_rn(0.1f, cache));      // 1 + ALPHA*cache
    mem = __fadd_rn(d, __fmul_rn(g, x));
    bool fired = (mem > 0.5f);                              // mem - V_TH > 0
    float spike = fired ? 1.0f : 0.0f;
    mem = fired ? 0.0f : mem;                               // hard reset to 0
    cache = __fadd_rn(__fmul_rn(0.5f, cache), fired ? 0.0f : 1.0f);
    return spike;
}

__device__ __forceinline__ void step4(float4 x, float4& mem, float4& cache,
                                      float4& s) {
    s.x = lif_step(x.x, mem.x, cache.x);
    s.y = lif_step(x.y, mem.y, cache.y);
    s.z = lif_step(x.z, mem.z, cache.z);
    s.w = lif_step(x.w, mem.w, cache.w);
}

__device__ __forceinline__ int lane_base(int lane) {
    int b = lane >> 13;                 // lane / N4
    int c = lane & (N4 - 1);            // lane % N4
    return b * (T * N4) + c;
}

__global__ __launch_bounds__(THREADS) void lif_kernel(
    const float4* __restrict__ X, float4* __restrict__ out)
{
    int lane0 = blockIdx.x * THREADS + threadIdx.x;   // [0, HALF)
    int base0 = lane_base(lane0);
    int base1 = lane_base(lane0 + HALF);              // distant pages

    float4 mem0   = make_float4(0.f, 0.f, 0.f, 0.f);
    float4 cache0 = make_float4(0.f, 0.f, 0.f, 0.f);
    float4 mem1   = make_float4(0.f, 0.f, 0.f, 0.f);
    float4 cache1 = make_float4(0.f, 0.f, 0.f, 0.f);

    // Prefetch-by-1 pipeline on both streams.
    float4 x0 = __ldcs(&X[base0]);
    float4 x1 = __ldcs(&X[base1]);

#pragma unroll 4
    for (int t = 0; t < T; ++t) {
        int tn = min(t + 1, T - 1);
        float4 xn0 = __ldcs(&X[base0 + tn * N4]);   // 2 independent
        float4 xn1 = __ldcs(&X[base1 + tn * N4]);   // loads in flight

        float4 s0, s1;
        step4(x0, mem0, cache0, s0);
        step4(x1, mem1, cache1, s1);

        __stcs(&out[base0 + t * N4], s0);
        __stcs(&out[base1 + t * N4], s1);
        x0 = xn0;
        x1 = xn1;
    }
}

extern "C" void kernel_launch(void* const* d_in, const int* in_sizes, int n_in,
                              void* d_out, int out_size) {
    const float4* X = (const float4*)d_in[0];
    float4* out = (float4*)d_out;
    lif_kernel<<<CTAS, THREADS>>>(X, out);
}

// round 10
// speedup vs baseline: 1.0243x; 1.0007x over previous
#include <cuda_runtime.h>

// LIF neuron with cache term (final kernel — at the measured roofline):
//   mem   = mem/TAU + (1 + ALPHA*cache) * x_t
//   spike = (mem - V_TH > 0); mem = (1-spike)*mem; cache = BETA*cache + (1-spike)
//
// X: [B=32, T=64, N=32768] f32 -> spikes, same shape. Pure streaming,
// 512 MiB compulsory traffic, 1:1 read:write.
//
// Session conclusion (R4-R9): six mechanistically distinct variants
// (register-pipeline depth, L2 prefetch, cp.async SMEM ring, exact
// CTA balance, 256-bit v8 ops, dual distant address streams) all pin
// DRAM at 73-76% active / ~6.0 TB/s with kernel time 80.2-80.6 us.
// That is the B300 effective ceiling for a fine-grained 1:1 R/W mix
// (read<->write turnaround + refresh; the 8 TB/s spec is
// unidirectional). This kernel = best measured harness config (R3).
//
// Division by TAU=5 via residual-corrected FMA triple — provably
// bit-identical to __fdiv_rn(x,5) for all floats (true quotient is
// >= 1/10 ulp from any rounding midpoint; sequence error ~2^-25 ulp).
// All other ops use explicit __f*_rn (no FMA contraction) to
// bit-match the XLA reference — a single threshold flip would cascade
// down the whole T recurrence. rel_err has been exactly 0.0 on every
// run of this arithmetic path.

constexpr int B = 32;
constexpr int T = 64;
constexpr int N = 32768;
constexpr int N4 = N / 4;           // 8192 float4 per (b, t) row

__device__ __forceinline__ float div5_exact(float x) {
    const float y = 0.2f;                       // RN(1/5)
    float q = __fmul_rn(x, y);
    float r = __fmaf_rn(q, -5.0f, x);           // exact residual
    return __fmaf_rn(r, y, q);                  // == __fdiv_rn(x, 5.0f)
}

__device__ __forceinline__ float lif_step(float x, float& mem, float& cache) {
    float d = div5_exact(mem);                              // mem / TAU
    float g = __fadd_rn(1.0f, __fmul_rn(0.1f, cache));      // 1 + ALPHA*cache
    mem = __fadd_rn(d, __fmul_rn(g, x));
    bool fired = (mem > 0.5f);                              // mem - V_TH > 0
    float spike = fired ? 1.0f : 0.0f;
    mem = fired ? 0.0f : mem;                               // hard reset to 0
    cache = __fadd_rn(__fmul_rn(0.5f, cache), fired ? 0.0f : 1.0f);
    return spike;
}

__global__ __launch_bounds__(256) void lif_kernel(
    const float4* __restrict__ X, float4* __restrict__ out)
{
    int lane = blockIdx.x * blockDim.x + threadIdx.x;   // [0, B*N4)
    int b = lane >> 13;                                  // lane / N4
    int c = lane & (N4 - 1);                             // lane % N4
    int base = b * (T * N4) + c;

    float4 mem   = make_float4(0.f, 0.f, 0.f, 0.f);
    float4 cache = make_float4(0.f, 0.f, 0.f, 0.f);

    // Prefetch pipeline: x holds the data for step t; the load for
    // step t+1 is issued before the step-t compute body.
    float4 x = __ldcs(&X[base]);

#pragma unroll 8
    for (int t = 0; t < T; ++t) {
        int tn = min(t + 1, T - 1);               // branchless clamp
        float4 xn = __ldcs(&X[base + tn * N4]);   // in flight during compute

        float4 s;
        s.x = lif_step(x.x, mem.x, cache.x);
        s.y = lif_step(x.y, mem.y, cache.y);
        s.z = lif_step(x.z, mem.z, cache.z);
        s.w = lif_step(x.w, mem.w, cache.w);

        __stcs(&out[base + t * N4], s);
        x = xn;
    }
}

extern "C" void kernel_launch(void* const* d_in, const int* in_sizes, int n_in,
                              void* d_out, int out_size) {
    const float4* X = (const float4*)d_in[0];
    float4* out = (float4*)d_out;
    int lanes = B * N4;                 // 262,144
    lif_kernel<<<lanes / 256, 256>>>(X, out);
}